// round 11
// baseline (speedup 1.0000x reference)
#include <cuda_runtime.h>

// LightweightConv: depthwise temporal conv with per-head softmax weights.
// B=16, T=4000, C=512, H=8, K=31, PAD=15.
// out[b,t,c] = sum_k softmax(w)[c%8][k] * x[b, t-15+k, c] + bias[c%8]
//
// R11: single fused kernel. Each block computes the (tiny) softmax in a
// warp-parallel prologue (~300cyc), packs per-pair weights in SMEM, then
// copies them to resident registers and runs the proven R6/TT=24 main loop.
// Eliminates the prep launch + second graph node (~5-6us of E2E).

#define B_ 16
#define T_ 4000
#define C_ 512
#define H_ 8
#define K_ 31
#define PAD_ 15
#define TT 24   // t-outputs per thread; ceil(4000/24) = 167 blocks in t

// Packed fp32x2 FMA (sm_100+): d = a*b + c elementwise on two packed floats.
__device__ __forceinline__ unsigned long long ffma2(unsigned long long a,
                                                    unsigned long long b,
                                                    unsigned long long c) {
    unsigned long long d;
    asm("fma.rn.f32x2 %0, %1, %2, %3;" : "=l"(d) : "l"(a), "l"(b), "l"(c));
    return d;
}

// Streaming 8B store (evict-first: output is never re-read; protect L2 halo).
__device__ __forceinline__ void stcs8(float* a, unsigned long long v) {
    asm volatile("st.global.cs.b64 [%0], %1;" :: "l"(a), "l"(v));
}

__device__ __forceinline__ unsigned long long pack2(float lo, float hi) {
    float2 v = make_float2(lo, hi);
    return *reinterpret_cast<unsigned long long*>(&v);
}

__global__ void __launch_bounds__(256, 2)
conv_kernel(const float* __restrict__ x, const float* __restrict__ w,
            const float* __restrict__ bias, float* __restrict__ out) {
    __shared__ float s_ws[H_][K_];                 // softmaxed weights
    __shared__ unsigned long long s_wp[4][K_];     // packed per pair-type
    __shared__ unsigned long long s_bp[4];         // packed bias

    const int tid = threadIdx.x;          // 0..255
    const int wid = tid >> 5;
    const int lid = tid & 31;

    // --- Prologue: warp-parallel softmax (warp h handles head h). ---
    if (wid < H_) {
        const float v = (lid < K_) ? w[wid * K_ + lid] : -3.402823466e38f;
        float m = v;
        #pragma unroll
        for (int o = 16; o > 0; o >>= 1)
            m = fmaxf(m, __shfl_xor_sync(0xffffffffu, m, o));
        const float e = (lid < K_) ? expf(v - m) : 0.0f;
        float s = e;
        #pragma unroll
        for (int o = 16; o > 0; o >>= 1)
            s += __shfl_xor_sync(0xffffffffu, s, o);
        if (lid < K_) s_ws[wid][lid] = e / s;
    }
    __syncthreads();
    if (tid < 4 * K_) {
        const int pp = tid / K_;
        const int kk = tid - pp * K_;
        s_wp[pp][kk] = pack2(s_ws[2 * pp][kk], s_ws[2 * pp + 1][kk]);
    }
    if (tid < 4) s_bp[tid] = pack2(bias[2 * tid], bias[2 * tid + 1]);
    __syncthreads();

    // --- Main body: identical structure to R6 (best: 49.0us). ---
    const int c0 = tid << 1;              // channels c0, c0+1 (contiguous)
    const int p = tid & 3;                // pair type: heads (2p, 2p+1)
    const int b = blockIdx.y;
    const int t0 = blockIdx.x * TT;

    // Copy packed weights into resident registers (one-time, before loop).
    unsigned long long wk[K_];
    #pragma unroll
    for (int k = 0; k < K_; k++) wk[k] = s_wp[p][k];

    const unsigned long long bb = s_bp[p];

    unsigned long long acc[TT];
    #pragma unroll
    for (int j = 0; j < TT; j++) acc[j] = bb;

    const float* xp = x + ((size_t)b * T_) * C_ + c0;

    if (t0 >= PAD_ && t0 + TT + PAD_ <= T_) {
        // Interior fast path: no boundary predicates.
        const float* xq = xp + (size_t)(t0 - PAD_) * C_;
        #pragma unroll
        for (int i = 0; i < TT + 2 * PAD_; i++) {
            const unsigned long long xv =
                *reinterpret_cast<const unsigned long long*>(xq + (size_t)i * C_);
            #pragma unroll
            for (int j = 0; j < TT; j++) {
                if (i - j >= 0 && i - j < K_)   // constant-folds after unroll
                    acc[j] = ffma2(wk[i - j], xv, acc[j]);
            }
        }
        float* op = out + ((size_t)b * T_ + t0) * C_ + c0;
        #pragma unroll
        for (int j = 0; j < TT; j++)
            stcs8(op + (size_t)j * C_, acc[j]);
    } else {
        // Boundary path: zero-padded loads, guarded stores (covers tail block).
        #pragma unroll
        for (int i = 0; i < TT + 2 * PAD_; i++) {
            const int t = t0 - PAD_ + i;
            unsigned long long xv = 0ull;
            if (t >= 0 && t < T_)
                xv = *reinterpret_cast<const unsigned long long*>(xp + (size_t)t * C_);
            #pragma unroll
            for (int j = 0; j < TT; j++) {
                if (i - j >= 0 && i - j < K_)
                    acc[j] = ffma2(wk[i - j], xv, acc[j]);
            }
        }
        float* op = out + ((size_t)b * T_ + t0) * C_ + c0;
        #pragma unroll
        for (int j = 0; j < TT; j++)
            if (t0 + j < T_)
                stcs8(op + (size_t)j * C_, acc[j]);
    }
}

extern "C" void kernel_launch(void* const* d_in, const int* in_sizes, int n_in,
                              void* d_out, int out_size) {
    const float* x    = (const float*)d_in[0];  // (B, T, C)
    const float* w    = (const float*)d_in[1];  // (H, 1, K)
    const float* bias = (const float*)d_in[2];  // (H,)
    float* out = (float*)d_out;                 // (B, T, C)

    dim3 grid((T_ + TT - 1) / TT, B_);
    conv_kernel<<<grid, 256>>>(x, w, bias, out);
}

// round 12
// speedup vs baseline: 1.0005x; 1.0005x over previous
#include <cuda_runtime.h>
#include <cstdint>

// LightweightConv: depthwise temporal conv with per-head softmax weights.
// B=16, T=4000, C=512, H=8, K=31, PAD=15.
// out[b,t,c] = sum_k softmax(w)[c%8][k] * x[b, t-15+k, c] + bias[c%8]
//
// R12: R6 compute loop (weights resident, TT=24, FFMA2, .cs stores) fed by
// cp.async.bulk (UBLKCP) -> 3-slot SMEM ring. Loads cost zero registers and
// zero per-thread issue slots -> FFMA2 pipe no longer throttled by MLP.

#define B_ 16
#define T_ 4000
#define C_ 512
#define H_ 8
#define K_ 31
#define PAD_ 15
#define TT 24            // outputs per thread; ceil(4000/24)=167 t-blocks
#define ROWB 2048        // bytes per x row (512 floats)
#define SLOT (16 * ROWB) // 32KB per ring slot (16 rows)

__device__ unsigned long long g_wpair[4][K_];
__device__ unsigned long long g_bpair[4];

__global__ void prep_kernel(const float* __restrict__ w,
                            const float* __restrict__ bias) {
    __shared__ float ws[H_][K_];
    int tid = threadIdx.x;
    if (tid < H_) {
        float m = -3.402823466e38f;
        #pragma unroll
        for (int k = 0; k < K_; k++) m = fmaxf(m, w[tid * K_ + k]);
        float e[K_];
        float s = 0.0f;
        #pragma unroll
        for (int k = 0; k < K_; k++) { e[k] = expf(w[tid * K_ + k] - m); s += e[k]; }
        float inv = 1.0f / s;
        #pragma unroll
        for (int k = 0; k < K_; k++) ws[tid][k] = e[k] * inv;
    }
    __syncthreads();
    if (tid < 4 * K_) {
        int p = tid / K_, k = tid % K_;
        float2 v = make_float2(ws[2 * p][k], ws[2 * p + 1][k]);
        g_wpair[p][k] = *reinterpret_cast<unsigned long long*>(&v);
    }
    if (tid < 4) {
        float2 v = make_float2(bias[2 * tid], bias[2 * tid + 1]);
        g_bpair[tid] = *reinterpret_cast<unsigned long long*>(&v);
    }
}

__device__ __forceinline__ unsigned long long ffma2(unsigned long long a,
                                                    unsigned long long b,
                                                    unsigned long long c) {
    unsigned long long d;
    asm("fma.rn.f32x2 %0, %1, %2, %3;" : "=l"(d) : "l"(a), "l"(b), "l"(c));
    return d;
}

__device__ __forceinline__ void stcs8(float* a, unsigned long long v) {
    asm volatile("st.global.cs.b64 [%0], %1;" :: "l"(a), "l"(v));
}

__device__ __forceinline__ unsigned smem_u32(const void* p) {
    unsigned a;
    asm("{ .reg .u64 t; cvta.to.shared.u64 t, %1; cvt.u32.u64 %0, t; }"
        : "=r"(a) : "l"(p));
    return a;
}

__device__ __forceinline__ void mbar_wait(uint64_t* bar, int phase) {
    unsigned addr = smem_u32(bar);
    asm volatile(
        "{\n\t.reg .pred P;\n\t"
        "W_%=: mbarrier.try_wait.parity.acquire.cta.shared::cta.b64 P, [%0], %1;\n\t"
        "@P bra D_%=;\n\t"
        "bra W_%=;\n\t"
        "D_%=:\n\t}"
        :: "r"(addr), "r"(phase) : "memory");
}

// Consume chunk C (rows 16C .. 16C+NC-1 of the block's 54-row span).
#define COMPUTE_CHUNK(C, NC)                                                  \
    do {                                                                      \
        const char* sbase = smem_dyn + ((C) % 3) * SLOT + (size_t)tid * 8;    \
        _Pragma("unroll")                                                     \
        for (int r = 0; r < (NC); r++) {                                      \
            const int i = 16 * (C) + r;                                       \
            const unsigned long long xv =                                     \
                *reinterpret_cast<const unsigned long long*>(sbase + r * ROWB);\
            _Pragma("unroll")                                                 \
            for (int j = 0; j < TT; j++) {                                    \
                if (i - j >= 0 && i - j < K_)                                 \
                    acc[j] = ffma2(wk[i - j], xv, acc[j]);                    \
            }                                                                 \
        }                                                                     \
    } while (0)

// Elected thread: expect_tx + bulk-copy chunk C (NBYTES) into its ring slot.
#define ISSUE_CHUNK(C, NBYTES)                                                \
    do {                                                                      \
        if (tid == 0) {                                                       \
            unsigned mb = smem_u32(&mbar[(C) % 3]);                           \
            asm volatile(                                                     \
                "mbarrier.arrive.expect_tx.shared::cta.b64 _, [%0], %1;"      \
                :: "r"(mb), "r"((unsigned)(NBYTES)) : "memory");              \
            const char* src = xrow0 + (size_t)(16 * (C)) * ROWB;              \
            unsigned dst = smem_u32(smem_dyn + ((C) % 3) * SLOT);             \
            asm volatile(                                                     \
                "cp.async.bulk.shared::cta.global.mbarrier::complete_tx::bytes"\
                " [%0], [%1], %2, [%3];"                                      \
                :: "r"(dst), "l"(src), "r"((unsigned)(NBYTES)), "r"(mb)       \
                : "memory");                                                  \
        }                                                                     \
    } while (0)

__global__ void __launch_bounds__(256, 2)
conv_kernel(const float* __restrict__ x, float* __restrict__ out) {
    extern __shared__ char smem_dyn[];          // 3 * 32KB ring
    __shared__ uint64_t mbar[3];

    const int tid = threadIdx.x;
    const int c0 = tid << 1;
    const int p = tid & 3;
    const int b = blockIdx.y;
    const int t0 = blockIdx.x * TT;

    // Weights resident in registers (proven best).
    unsigned long long wk[K_];
    #pragma unroll
    for (int k = 0; k < K_; k++) wk[k] = g_wpair[p][k];

    const unsigned long long bb = g_bpair[p];

    unsigned long long acc[TT];
    #pragma unroll
    for (int j = 0; j < TT; j++) acc[j] = bb;

    const bool interior = (t0 >= PAD_ && t0 + TT + PAD_ <= T_);

    if (interior) {
        if (tid == 0) {
            #pragma unroll
            for (int s = 0; s < 3; s++) {
                unsigned mb = smem_u32(&mbar[s]);
                asm volatile("mbarrier.init.shared.b64 [%0], 1;"
                             :: "r"(mb) : "memory");
            }
        }
        __syncthreads();

        const char* xrow0 = reinterpret_cast<const char*>(
            x + ((size_t)b * T_ + (t0 - PAD_)) * C_);

        // 54 rows = chunks of 16,16,16,6. Ring depth 3; chunk3 reuses slot0.
        ISSUE_CHUNK(0, 16 * ROWB);
        ISSUE_CHUNK(1, 16 * ROWB);
        ISSUE_CHUNK(2, 16 * ROWB);

        mbar_wait(&mbar[0], 0);
        COMPUTE_CHUNK(0, 16);
        __syncthreads();                 // slot 0 fully consumed by all warps
        ISSUE_CHUNK(3, 6 * ROWB);

        mbar_wait(&mbar[1], 0);
        COMPUTE_CHUNK(1, 16);

        mbar_wait(&mbar[2], 0);
        COMPUTE_CHUNK(2, 16);

        mbar_wait(&mbar[0], 1);
        COMPUTE_CHUNK(3, 6);

        float* op = out + ((size_t)b * T_ + t0) * C_ + c0;
        #pragma unroll
        for (int j = 0; j < TT; j++)
            stcs8(op + (size_t)j * C_, acc[j]);
    } else {
        // Boundary blocks (first/last): R6 LDG path, guarded loads/stores.
        const float* xp = x + ((size_t)b * T_) * C_ + c0;
        #pragma unroll
        for (int i = 0; i < TT + 2 * PAD_; i++) {
            const int t = t0 - PAD_ + i;
            unsigned long long xv = 0ull;
            if (t >= 0 && t < T_)
                xv = *reinterpret_cast<const unsigned long long*>(
                        xp + (size_t)t * C_);
            #pragma unroll
            for (int j = 0; j < TT; j++) {
                if (i - j >= 0 && i - j < K_)
                    acc[j] = ffma2(wk[i - j], xv, acc[j]);
            }
        }
        float* op = out + ((size_t)b * T_ + t0) * C_ + c0;
        #pragma unroll
        for (int j = 0; j < TT; j++)
            if (t0 + j < T_)
                stcs8(op + (size_t)j * C_, acc[j]);
    }
}

extern "C" void kernel_launch(void* const* d_in, const int* in_sizes, int n_in,
                              void* d_out, int out_size) {
    const float* x    = (const float*)d_in[0];  // (B, T, C)
    const float* w    = (const float*)d_in[1];  // (H, 1, K)
    const float* bias = (const float*)d_in[2];  // (H,)
    float* out = (float*)d_out;                 // (B, T, C)

    static bool attr_set = false;
    if (!attr_set) {
        cudaFuncSetAttribute(conv_kernel,
                             cudaFuncAttributeMaxDynamicSharedMemorySize,
                             3 * SLOT);
        attr_set = true;
    }

    prep_kernel<<<1, 128>>>(w, bias);

    dim3 grid((T_ + TT - 1) / TT, B_);
    conv_kernel<<<grid, 256, 3 * SLOT>>>(x, out);
}

// round 13
// speedup vs baseline: 1.1445x; 1.1439x over previous
#include <cuda_runtime.h>

// LightweightConv: depthwise temporal conv with per-head softmax weights.
// B=16, T=4000, C=512, H=8, K=31, PAD=15.
// out[b,t,c] = sum_k softmax(w)[c%8][k] * x[b, t-15+k, c] + bias[c%8]
//
// FINAL (= R6, best of 12 structural variants at 49.0us kernel):
//  - thread <-> contiguous channel pair, one LDG.64 + FFMA2 (fma.rn.f32x2)
//    per (row, output) covering both channels
//  - softmaxed weights packed per pair-type, resident in registers
//  - TT=24 outputs/thread (halo factor 2.25; optimum of TT sweep)
//  - streaming .cs stores (output never re-read; preserves L2 halo)
//  - 2 CTAs/SM. Falsified alternatives: higher occupancy, SMEM/JIT/K-split
//    weights, LDGSTS & TMA pipelines, L2 prefetch, fused softmax.

#define B_ 16
#define T_ 4000
#define C_ 512
#define H_ 8
#define K_ 31
#define PAD_ 15
#define TT 24   // t-outputs per thread; ceil(4000/24) = 167 blocks in t

// Packed (per channel-pair) softmaxed weights and bias.
// Pair type p in [0,4): channels (2p, 2p+1) mod 8 -> heads (2p, 2p+1).
__device__ unsigned long long g_wpair[4][K_];
__device__ unsigned long long g_bpair[4];

__global__ void prep_kernel(const float* __restrict__ w,
                            const float* __restrict__ bias) {
    __shared__ float ws[H_][K_];
    int tid = threadIdx.x;
    if (tid < H_) {
        float m = -3.402823466e38f;
        #pragma unroll
        for (int k = 0; k < K_; k++) m = fmaxf(m, w[tid * K_ + k]);
        float e[K_];
        float s = 0.0f;
        #pragma unroll
        for (int k = 0; k < K_; k++) {
            e[k] = expf(w[tid * K_ + k] - m);
            s += e[k];
        }
        float inv = 1.0f / s;
        #pragma unroll
        for (int k = 0; k < K_; k++) ws[tid][k] = e[k] * inv;
    }
    __syncthreads();
    if (tid < 4 * K_) {
        int p = tid / K_;
        int k = tid % K_;
        float2 v = make_float2(ws[2 * p][k], ws[2 * p + 1][k]);
        g_wpair[p][k] = *reinterpret_cast<unsigned long long*>(&v);
    }
    if (tid < 4) {
        float2 v = make_float2(bias[2 * tid], bias[2 * tid + 1]);
        g_bpair[tid] = *reinterpret_cast<unsigned long long*>(&v);
    }
}

// Packed fp32x2 FMA (sm_100+): d = a*b + c elementwise on two packed floats.
__device__ __forceinline__ unsigned long long ffma2(unsigned long long a,
                                                    unsigned long long b,
                                                    unsigned long long c) {
    unsigned long long d;
    asm("fma.rn.f32x2 %0, %1, %2, %3;" : "=l"(d) : "l"(a), "l"(b), "l"(c));
    return d;
}

// Streaming 8B store (evict-first: output is never re-read; protect L2 halo).
__device__ __forceinline__ void stcs8(float* a, unsigned long long v) {
    asm volatile("st.global.cs.b64 [%0], %1;" :: "l"(a), "l"(v));
}

__global__ void __launch_bounds__(256, 2)
conv_kernel(const float* __restrict__ x, float* __restrict__ out) {
    const int tid = threadIdx.x;          // 0..255
    const int c0 = tid << 1;              // channels c0, c0+1 (contiguous)
    const int p = tid & 3;                // pair type: heads (2p, 2p+1)
    const int b = blockIdx.y;
    const int t0 = blockIdx.x * TT;

    // Weights for this channel pair (packed), resident in registers.
    unsigned long long wk[K_];
    #pragma unroll
    for (int k = 0; k < K_; k++) wk[k] = g_wpair[p][k];

    const unsigned long long bb = g_bpair[p];

    unsigned long long acc[TT];
    #pragma unroll
    for (int j = 0; j < TT; j++) acc[j] = bb;

    const float* xp = x + ((size_t)b * T_) * C_ + c0;

    if (t0 >= PAD_ && t0 + TT + PAD_ <= T_) {
        // Interior fast path: no boundary predicates.
        const float* xq = xp + (size_t)(t0 - PAD_) * C_;
        #pragma unroll
        for (int i = 0; i < TT + 2 * PAD_; i++) {
            const unsigned long long xv =
                *reinterpret_cast<const unsigned long long*>(xq + (size_t)i * C_);
            #pragma unroll
            for (int j = 0; j < TT; j++) {
                if (i - j >= 0 && i - j < K_)   // constant-folds after unroll
                    acc[j] = ffma2(wk[i - j], xv, acc[j]);
            }
        }
        float* op = out + ((size_t)b * T_ + t0) * C_ + c0;
        #pragma unroll
        for (int j = 0; j < TT; j++)
            stcs8(op + (size_t)j * C_, acc[j]);
    } else {
        // Boundary path: zero-padded loads, guarded stores (covers tail block).
        #pragma unroll
        for (int i = 0; i < TT + 2 * PAD_; i++) {
            const int t = t0 - PAD_ + i;
            unsigned long long xv = 0ull;
            if (t >= 0 && t < T_)
                xv = *reinterpret_cast<const unsigned long long*>(xp + (size_t)t * C_);
            #pragma unroll
            for (int j = 0; j < TT; j++) {
                if (i - j >= 0 && i - j < K_)
                    acc[j] = ffma2(wk[i - j], xv, acc[j]);
            }
        }
        float* op = out + ((size_t)b * T_ + t0) * C_ + c0;
        #pragma unroll
        for (int j = 0; j < TT; j++)
            if (t0 + j < T_)
                stcs8(op + (size_t)j * C_, acc[j]);
    }
}

extern "C" void kernel_launch(void* const* d_in, const int* in_sizes, int n_in,
                              void* d_out, int out_size) {
    const float* x    = (const float*)d_in[0];  // (B, T, C)
    const float* w    = (const float*)d_in[1];  // (H, 1, K)
    const float* bias = (const float*)d_in[2];  // (H,)
    float* out = (float*)d_out;                 // (B, T, C)

    prep_kernel<<<1, 128>>>(w, bias);

    dim3 grid((T_ + TT - 1) / TT, B_);
    conv_kernel<<<grid, 256>>>(x, out);
}